// round 15
// baseline (speedup 1.0000x reference)
#include <cuda_runtime.h>
#include <cuda_fp16.h>
#include <math.h>
#include <stdint.h>

#define NMAX   50000
#define EMAX   600000
#define OUTT   349

// ---------------- scratch (device globals) ----------------------------------
__device__ int    g_deg[NMAX];
__device__ float  g_dinv[NMAX];
__device__ int    g_off[NMAX];
__device__ int    g_cur[NMAX];
__device__ int    g_adj[EMAX];
__device__ float  g_adjd[EMAX];
__device__ int    g_total;
__device__ __half g_linh[(size_t)NMAX * 176];   // bases (fp16), pitch = NBF
__device__ float  g_linc[(size_t)NMAX * 96];    // comb (fp32), pitch = 96
__device__ __half g_xh[(size_t)NMAX * 128];
__device__ __half g_hA[(size_t)NMAX * 256];
__device__ __half g_hB[(size_t)NMAX * 256];
__device__ __half g_wt0[224 * 128];
__device__ __half g_wt1[224 * 256];
__device__ __half g_wt2[288 * 256];

// ---------------- PDL helpers --------------------------------------------------
__device__ __forceinline__ void gdc_wait()  { asm volatile("griddepcontrol.wait;" ::: "memory"); }
__device__ __forceinline__ void gdc_launch(){ asm volatile("griddepcontrol.launch_dependents;" ::: "memory"); }

// ---------------- converts ----------------------------------------------------
__device__ __forceinline__ void cvt_one(const float* Wb, const float* Wc, __half* Wt,
                                        int idx, int K, int NBF, int Ntot) {
    int n = idx / K, k = idx % K;
    float v = 0.0f;
    if (n < NBF)       v = Wb[k * NBF + n];
    else if (n < Ntot) v = Wc[k * (Ntot - NBF) + (n - NBF)];
    Wt[idx] = __float2half_rn(v);
}

__global__ void k_cvt_xw0(const float* __restrict__ x, __half2* __restrict__ xh, int n4,
                          const float* __restrict__ Wb0, const float* __restrict__ Wc0,
                          __half* __restrict__ wt0) {
    int i = blockIdx.x * blockDim.x + threadIdx.x;
    if (i < n4) {
        float4 v = reinterpret_cast<const float4*>(x)[i];
        xh[2 * i]     = __floats2half2_rn(v.x, v.y);
        xh[2 * i + 1] = __floats2half2_rn(v.z, v.w);
    } else {
        int idx = i - n4;
        if (idx < 224 * 128) cvt_one(Wb0, Wc0, wt0, idx, 128, 128, 224);
    }
    gdc_launch();
}

__global__ void k_cvt_w12(const float* __restrict__ Wb1, const float* __restrict__ Wc1,
                          const float* __restrict__ Wb2, const float* __restrict__ Wc2,
                          __half* __restrict__ wt1, __half* __restrict__ wt2) {
    const int S1 = 224 * 256, S2 = 288 * 256;
    int idx = blockIdx.x * blockDim.x + threadIdx.x;
    if (idx < S1)           cvt_one(Wb1, Wc1, wt1, idx,      256, 128, 224);
    else if (idx < S1 + S2) cvt_one(Wb2, Wc2, wt2, idx - S1, 256, 176, 272);
}

// ---------------- CSR build (scalar, high-occupancy, PDL edges) ---------------
__global__ void k_zero(int n) {
    int i = blockIdx.x * blockDim.x + threadIdx.x;
    if (i < n) g_deg[i] = 0;
    if (blockIdx.x == 0 && threadIdx.x == 0) g_total = 0;
    gdc_launch();
}

__global__ void k_deg(const int* __restrict__ row, int e) {
    int i = blockIdx.x * blockDim.x + threadIdx.x;
    int r = (i < e) ? row[i] : 0;
    gdc_wait();
    if (i < e) atomicAdd(&g_deg[r], 1);
    gdc_launch();
}

__global__ void k_off(int n) {
    int i = blockIdx.x * blockDim.x + threadIdx.x;
    int lane = threadIdx.x & 31;
    gdc_wait();
    int d = (i < n) ? g_deg[i] : 0;
    int s = d;
#pragma unroll
    for (int o = 1; o < 32; o <<= 1) {
        int u = __shfl_up_sync(0xffffffffu, s, o);
        if (lane >= o) s += u;
    }
    int total = __shfl_sync(0xffffffffu, s, 31);
    int base = 0;
    if (lane == 0) base = atomicAdd(&g_total, total);
    base = __shfl_sync(0xffffffffu, base, 0);
    if (i < n) {
        int off = base + s - d;
        g_off[i] = off;
        g_cur[i] = off;
        g_dinv[i] = (d > 0) ? rsqrtf((float)d) : 0.0f;
    }
    gdc_launch();
}

__global__ void k_scatter(const int* __restrict__ row, const int* __restrict__ col, int e) {
    int i = blockIdx.x * blockDim.x + threadIdx.x;
    int r = 0, c = 0;
    if (i < e) { r = row[i]; c = col[i]; }
    gdc_wait();
    if (i < e) {
        int p = atomicAdd(&g_cur[r], 1);
        g_adj[p]  = c;
        g_adjd[p] = g_dinv[c];
    }
}

// ---------------- fp16 tensor-core GEMM, cp.async + ldmatrix + PDL ------------
__device__ __forceinline__ void mma16(float* c, const uint32_t* a, const uint32_t* b) {
    asm volatile(
        "mma.sync.aligned.m16n8k16.row.col.f32.f16.f16.f32 "
        "{%0,%1,%2,%3}, {%4,%5,%6,%7}, {%8,%9}, {%0,%1,%2,%3};"
        : "+f"(c[0]), "+f"(c[1]), "+f"(c[2]), "+f"(c[3])
        : "r"(a[0]), "r"(a[1]), "r"(a[2]), "r"(a[3]), "r"(b[0]), "r"(b[1]));
}

__device__ __forceinline__ void cpa16(uint32_t saddr, const void* gptr, bool pred) {
    int sz = pred ? 16 : 0;
    asm volatile("cp.async.ca.shared.global [%0], [%1], 16, %2;"
                 :: "r"(saddr), "l"(gptr), "r"(sz));
}

__device__ __forceinline__ void ldsm4(uint32_t& a, uint32_t& b, uint32_t& c, uint32_t& d,
                                      uint32_t addr) {
    asm volatile("ldmatrix.sync.aligned.m8n8.x4.shared.b16 {%0,%1,%2,%3}, [%4];"
                 : "=r"(a), "=r"(b), "=r"(c), "=r"(d) : "r"(addr));
}
__device__ __forceinline__ void ldsm2(uint32_t& a, uint32_t& b, uint32_t addr) {
    asm volatile("ldmatrix.sync.aligned.m8n8.x2.shared.b16 {%0,%1}, [%2];"
                 : "=r"(a), "=r"(b) : "r"(addr));
}

template<int NT>
__global__ __launch_bounds__(256)
void k_gemm_h(const __half* __restrict__ A, const __half* __restrict__ Wt,
              const float* __restrict__ bc,
              __half* __restrict__ Ch, float* __restrict__ Cc,
              int M, int K, int NBF, int Ntot)
{
    constexpr int BN    = 16 * NT;
    constexpr int NPAIR = NT / 2;
    constexpr int TAIL  = NT & 1;
    __shared__ __align__(16) uint32_t As[4][128][12];
    __shared__ __align__(16) uint32_t Bs[4][BN][12];

    const int tid  = threadIdx.x;
    const int bm   = blockIdx.y * 128;
    const int bn   = blockIdx.x * BN;
    const int w    = tid >> 5, lane = tid & 31;
    const int wm   = w & 3,   wn   = w >> 2;
    const int g    = lane >> 2, t4 = lane & 3;

    const int crow = tid >> 1, ch = tid & 1;
    const bool aval = (bm + crow) < M;
    const __half* agp = A  + (size_t)(bm + crow) * K + ch * 8;
    const __half* bgp = Wt + (size_t)(bn + crow) * K + ch * 8;
    const bool bv = (tid < 2 * BN);

    uint32_t a_s = (uint32_t)__cvta_generic_to_shared(&As[0][crow][ch * 4]);
    uint32_t b_s = (uint32_t)__cvta_generic_to_shared(&Bs[0][crow][ch * 4]);
    constexpr uint32_t ASTRIDE = 128 * 12 * 4;
    constexpr uint32_t BSTRIDE = BN * 12 * 4;

    const int rm0 = wm * 32;
    const int cn0 = wn * NT * 8;

    const int arow = rm0 + ((lane >> 3) & 1) * 8 + (lane & 7);
    const int awrd = (lane >> 4) * 4;
    const uint32_t sA0 = (uint32_t)__cvta_generic_to_shared(&As[0][arow][awrd]);
    uint32_t sB[NPAIR + TAIL];
#pragma unroll
    for (int p = 0; p < NPAIR; p++) {
        int brow = cn0 + p * 16 + ((lane >> 4) & 1) * 8 + (lane & 7);
        int bwrd = ((lane >> 3) & 1) * 4;
        sB[p] = (uint32_t)__cvta_generic_to_shared(&Bs[0][brow][bwrd]);
    }
    if (TAIL) {
        int brow = cn0 + NPAIR * 16 + (lane & 7);
        int bwrd = ((lane >> 3) & 1) * 4;
        sB[NPAIR] = (uint32_t)__cvta_generic_to_shared(&Bs[0][brow][bwrd]);
    }

#define ISSUE(S, K0)                                                   \
    do {                                                               \
        cpa16(a_s + (S) * ASTRIDE, agp + (K0), aval);                  \
        if (bv) cpa16(b_s + (S) * BSTRIDE, bgp + (K0), true);          \
        asm volatile("cp.async.commit_group;");                        \
    } while (0)

    float acc[2][NT][4];
#pragma unroll
    for (int i = 0; i < 2; i++)
#pragma unroll
        for (int j = 0; j < NT; j++)
#pragma unroll
            for (int r = 0; r < 4; r++) acc[i][j][r] = 0.0f;

    gdc_wait();

    const int kiter = K >> 4;
    ISSUE(0, 0);
    ISSUE(1, 16);
    ISSUE(2, 32);

    for (int it = 0; it < kiter; it++) {
        asm volatile("cp.async.wait_group 2;");
        __syncthreads();
        const uint32_t aoff = (uint32_t)(it & 3) * ASTRIDE;
        const uint32_t boff = (uint32_t)(it & 3) * BSTRIDE;
        {
            uint32_t af0[4], af1[4];
            ldsm4(af0[0], af0[1], af0[2], af0[3], sA0 + aoff);
            ldsm4(af1[0], af1[1], af1[2], af1[3], sA0 + aoff + 16 * 48);
            uint32_t bf[NT][2];
#pragma unroll
            for (int p = 0; p < NPAIR; p++)
                ldsm4(bf[2 * p][0], bf[2 * p][1], bf[2 * p + 1][0], bf[2 * p + 1][1],
                      sB[p] + boff);
            if (TAIL)
                ldsm2(bf[NT - 1][0], bf[NT - 1][1], sB[NPAIR] + boff);
#pragma unroll
            for (int j = 0; j < NT; j++) {
                mma16(acc[0][j], af0, bf[j]);
                mma16(acc[1][j], af1, bf[j]);
            }
        }
        if (it + 3 < kiter) ISSUE((it + 3) & 3, (it + 3) * 16);
        else asm volatile("cp.async.commit_group;");
    }
#undef ISSUE

    gdc_launch();

    // ---- epilogue ----
#pragma unroll
    for (int i = 0; i < 2; i++) {
        int r0 = bm + rm0 + i * 16 + g;
#pragma unroll
        for (int j = 0; j < NT; j++) {
            int col = bn + cn0 + j * 8 + 2 * t4;
            if (col >= Ntot) continue;
            if (col < NBF) {
                if (r0 < M) {
                    __half2 h = __floats2half2_rn(acc[i][j][0], acc[i][j][1]);
                    *reinterpret_cast<__half2*>(&Ch[(size_t)r0 * NBF + col]) = h;
                }
                if (r0 + 8 < M) {
                    __half2 h = __floats2half2_rn(acc[i][j][2], acc[i][j][3]);
                    *reinterpret_cast<__half2*>(&Ch[(size_t)(r0 + 8) * NBF + col]) = h;
                }
            } else {
                int cc = col - NBF;
                float b0 = bc[cc], b1 = bc[cc + 1];
                if (r0 < M) {
                    float2 v = make_float2(acc[i][j][0] + b0, acc[i][j][1] + b1);
                    *reinterpret_cast<float2*>(&Cc[(size_t)r0 * 96 + cc]) = v;
                }
                if (r0 + 8 < M) {
                    float2 v = make_float2(acc[i][j][2] + b0, acc[i][j][3] + b1);
                    *reinterpret_cast<float2*>(&Cc[(size_t)(r0 + 8) * 96 + cc]) = v;
                }
            }
        }
    }
}

// ---------------- fused aggregation + combine + bias (+relu / +log_softmax) --
__device__ __forceinline__ float4 h4f(uint2 u) {
    __half2 a = *reinterpret_cast<__half2*>(&u.x);
    __half2 b = *reinterpret_cast<__half2*>(&u.y);
    float2 fa = __half22float2(a), fb = __half22float2(b);
    return make_float4(fa.x, fa.y, fb.x, fb.y);
}

template<int NBF, int F, bool RELU, bool LSM>
__global__ __launch_bounds__(256)
void k_agg(const __half* __restrict__ linh, const float* __restrict__ linc,
           const float* __restrict__ bias, void* __restrict__ out_v, int n)
{
    constexpr int HF  = 8 * F;
    constexpr int NI  = HF / 32;
    constexpr int NH4 = NBF / 4;
    constexpr int C4  = (NH4 + 31) / 32;
    constexpr int UN  = (C4 == 1) ? 8 : 4;
    __shared__ float agg_s[8][3 * NBF];
    __shared__ float comb_s[8][96];

    int gw   = (blockIdx.x * 256 + threadIdx.x) >> 5;
    int lane = threadIdx.x & 31;
    int lw   = threadIdx.x >> 5;
    if (gw >= n) { gdc_wait(); gdc_launch(); return; }

    int s = g_off[gw];
    int deg = g_deg[gw];
    int e = s + deg;

    float4 vsym[C4], vsum[C4], vmax[C4];
#pragma unroll
    for (int q = 0; q < C4; q++) {
        vsym[q] = make_float4(0.f, 0.f, 0.f, 0.f);
        vsum[q] = make_float4(0.f, 0.f, 0.f, 0.f);
        vmax[q] = make_float4(-INFINITY, -INFINITY, -INFINITY, -INFINITY);
    }

    gdc_wait();

    // Fully masked batched loop: no scalar tail. Invalid lanes reload the
    // batch's first row (L1 hit) with zero weight; max is masked by select.
    for (int t = s; t < e; t += UN) {
        int rem = e - t;
        int cc[UN]; float dd[UN], mw[UN]; const uint2* sp[UN];
#pragma unroll
        for (int u = 0; u < UN; u++) {
            bool vl = (u < rem);
            int idx = vl ? (t + u) : t;
            cc[u] = g_adj[idx];
            dd[u] = vl ? g_adjd[idx] : 0.0f;
            mw[u] = vl ? 1.0f : 0.0f;
            sp[u] = reinterpret_cast<const uint2*>(linh + (size_t)cc[u] * NBF);
        }
#pragma unroll
        for (int q = 0; q < C4; q++) {
            int i4 = lane + q * 32;
            if (C4 > 1 && i4 >= NH4) break;
            float4 vv[UN];
#pragma unroll
            for (int u = 0; u < UN; u++) vv[u] = h4f(sp[u][i4]);
#pragma unroll
            for (int u = 0; u < UN; u++) {
                vsym[q].x += dd[u] * vv[u].x; vsym[q].y += dd[u] * vv[u].y;
                vsym[q].z += dd[u] * vv[u].z; vsym[q].w += dd[u] * vv[u].w;
                vsum[q].x = fmaf(mw[u], vv[u].x, vsum[q].x);
                vsum[q].y = fmaf(mw[u], vv[u].y, vsum[q].y);
                vsum[q].z = fmaf(mw[u], vv[u].z, vsum[q].z);
                vsum[q].w = fmaf(mw[u], vv[u].w, vsum[q].w);
                vmax[q].x = fmaxf(vmax[q].x, (mw[u] > 0.f) ? vv[u].x : -INFINITY);
                vmax[q].y = fmaxf(vmax[q].y, (mw[u] > 0.f) ? vv[u].y : -INFINITY);
                vmax[q].z = fmaxf(vmax[q].z, (mw[u] > 0.f) ? vv[u].z : -INFINITY);
                vmax[q].w = fmaxf(vmax[q].w, (mw[u] > 0.f) ? vv[u].w : -INFINITY);
            }
        }
    }

    gdc_launch();

    float dn   = g_dinv[gw];
    float invd = (deg > 0) ? (1.0f / (float)deg) : 0.0f;

    float4* arow0 = reinterpret_cast<float4*>(&agg_s[lw][0]);
    float4* arow1 = reinterpret_cast<float4*>(&agg_s[lw][NBF]);
    float4* arow2 = reinterpret_cast<float4*>(&agg_s[lw][2 * NBF]);
#pragma unroll
    for (int q = 0; q < C4; q++) {
        int i4 = lane + q * 32;
        if (C4 > 1 && i4 >= NH4) break;
        float4 sy = vsym[q];
        sy.x *= dn; sy.y *= dn; sy.z *= dn; sy.w *= dn;
        float4 me = vsum[q];
        me.x *= invd; me.y *= invd; me.z *= invd; me.w *= invd;
        float4 mx = vmax[q];
        if (deg == 0) mx = make_float4(0.f, 0.f, 0.f, 0.f);
        arow0[i4] = sy;
        arow1[i4] = me;
        arow2[i4] = mx;
    }

    const float* comb = linc + (size_t)gw * 96;
    comb_s[lw][lane]      = comb[lane];
    comb_s[lw][lane + 32] = comb[lane + 32];
    comb_s[lw][lane + 64] = comb[lane + 64];
    __syncwarp();

    float vals[NI];
#pragma unroll
    for (int i = 0; i < NI; i++) {
        int c = lane + i * 32;
        int h = c / F, f = c % F;
        float v = bias[c];
        const float* cb = &comb_s[lw][h * 12];
        const float* ag = &agg_s[lw][0];
#pragma unroll
        for (int k = 0; k < 12; k++) v = fmaf(cb[k], ag[k * F + f], v);
        if (RELU) v = fmaxf(v, 0.0f);
        vals[i] = v;
    }

    if (!LSM) {
        __half* out = (__half*)out_v;
#pragma unroll
        for (int i = 0; i < NI; i++)
            out[(size_t)gw * HF + lane + i * 32] = __float2half_rn(vals[i]);
    } else {
        float* out = (float*)out_v;
        float m = -INFINITY;
#pragma unroll
        for (int i = 0; i < NI; i++) {
            int c = lane + i * 32;
            m = fmaxf(m, (c < OUTT) ? vals[i] : -INFINITY);
        }
#pragma unroll
        for (int o = 16; o; o >>= 1) m = fmaxf(m, __shfl_xor_sync(0xffffffffu, m, o));
        float sum = 0.0f;
#pragma unroll
        for (int i = 0; i < NI; i++) {
            int c = lane + i * 32;
            if (c < OUTT) sum += expf(vals[i] - m);
        }
#pragma unroll
        for (int o = 16; o; o >>= 1) sum += __shfl_xor_sync(0xffffffffu, sum, o);
        float l = m + logf(sum);
#pragma unroll
        for (int i = 0; i < NI; i++) {
            int c = lane + i * 32;
            if (c < OUTT) out[(size_t)gw * OUTT + c] = vals[i] - l;
        }
    }
}

// ---------------- launch --------------------------------------------------------
extern "C" void kernel_launch(void* const* d_in, const int* in_sizes, int n_in,
                              void* d_out, int out_size)
{
    const float* x   = (const float*)d_in[0];
    const int*   ei  = (const int*)d_in[1];
    int N = in_sizes[0] / 128;
    int E = in_sizes[1] / 2;
    if (N > NMAX) N = NMAX;
    if (E > EMAX) E = EMAX;
    const int* row = ei;
    const int* col = ei + E;

    const float* Wb0 = (const float*)d_in[2];
    const float* Wc0 = (const float*)d_in[3];
    const float* bc0 = (const float*)d_in[4];
    const float* b0  = (const float*)d_in[5];
    const float* Wb1 = (const float*)d_in[6];
    const float* Wc1 = (const float*)d_in[7];
    const float* bc1 = (const float*)d_in[8];
    const float* b1  = (const float*)d_in[9];
    const float* Wb2 = (const float*)d_in[10];
    const float* Wc2 = (const float*)d_in[11];
    const float* bc2 = (const float*)d_in[12];
    const float* b2  = (const float*)d_in[13];

    __half* linh; float* linc; __half* xh; __half* hA; __half* hB;
    __half* wt0; __half* wt1; __half* wt2;
    cudaGetSymbolAddress((void**)&linh, g_linh);
    cudaGetSymbolAddress((void**)&linc, g_linc);
    cudaGetSymbolAddress((void**)&xh,   g_xh);
    cudaGetSymbolAddress((void**)&hA,   g_hA);
    cudaGetSymbolAddress((void**)&hB,   g_hB);
    cudaGetSymbolAddress((void**)&wt0,  g_wt0);
    cudaGetSymbolAddress((void**)&wt1,  g_wt1);
    cudaGetSymbolAddress((void**)&wt2,  g_wt2);

    const int T   = 256;
    const int gy  = (N + 127) / 128;
    const int ab  = (N + 7) / 8;
    const int n4  = N * 128 / 4;
    const int W12 = 224 * 256 + 288 * 256;
    const int XW0 = n4 + 224 * 128;

    // Streams/events created ONCE (first call is uncaptured).
    static cudaStream_t s1 = nullptr, s2 = nullptr;
    static cudaEvent_t evRoot = nullptr, evCsr = nullptr, evW12 = nullptr;
    if (!s1) {
        cudaStreamCreateWithFlags(&s1, cudaStreamNonBlocking);
        cudaStreamCreateWithFlags(&s2, cudaStreamNonBlocking);
        cudaEventCreateWithFlags(&evRoot, cudaEventDisableTiming);
        cudaEventCreateWithFlags(&evCsr,  cudaEventDisableTiming);
        cudaEventCreateWithFlags(&evW12,  cudaEventDisableTiming);
    }

    cudaEventRecord(evRoot, 0);
    cudaStreamWaitEvent(s1, evRoot, 0);
    cudaStreamWaitEvent(s2, evRoot, 0);

    // PDL attribute
    cudaLaunchAttribute attrs[1];
    attrs[0].id = cudaLaunchAttributeProgrammaticStreamSerialization;
    attrs[0].val.programmaticStreamSerializationAllowed = 1;

    // s1: CSR build, scalar kernels (full occupancy) + programmatic edges
    cudaLaunchConfig_t cfg1 = {};
    cfg1.stream = s1;
    cfg1.attrs = attrs;
    cfg1.numAttrs = 1;
    cfg1.blockDim = dim3(256);

    cfg1.gridDim = dim3((N + T - 1) / T);
    cudaLaunchKernelEx(&cfg1, k_zero, N);
    cfg1.gridDim = dim3((E + T - 1) / T);
    cudaLaunchKernelEx(&cfg1, k_deg, row, E);
    cfg1.gridDim = dim3((N + T - 1) / T);
    cudaLaunchKernelEx(&cfg1, k_off, N);
    cfg1.gridDim = dim3((E + T - 1) / T);
    cudaLaunchKernelEx(&cfg1, k_scatter, row, col, E);
    cudaEventRecord(evCsr, s1);

    // s2: layer-1/2 weight converts
    k_cvt_w12<<<(W12 + T - 1) / T, T, 0, s2>>>(Wb1, Wc1, Wb2, Wc2, wt1, wt2);
    cudaEventRecord(evW12, s2);

    // main chain (stream 0) with PDL edges
    cudaLaunchConfig_t cfg = {};
    cfg.stream = 0;
    cfg.attrs = attrs;
    cfg.numAttrs = 1;
    cfg.blockDim = dim3(256);

    k_cvt_xw0<<<(XW0 + T - 1) / T, T>>>(x, (__half2*)xh, n4, Wb0, Wc0, wt0);

    cfg.gridDim = dim3(2, gy);
    cudaLaunchKernelEx(&cfg, k_gemm_h<7>, (const __half*)xh, (const __half*)wt0,
                       bc0, linh, linc, N, 128, 128, 224);

    cudaStreamWaitEvent(0, evCsr, 0);
    cudaStreamWaitEvent(0, evW12, 0);

    cfg.gridDim = dim3(ab);
    cudaLaunchKernelEx(&cfg, k_agg<128, 32, true, false>,
                       (const __half*)linh, (const float*)linc, b0, (void*)hA, N);

    cfg.gridDim = dim3(2, gy);
    cudaLaunchKernelEx(&cfg, k_gemm_h<7>, (const __half*)hA, (const __half*)wt1,
                       bc1, linh, linc, N, 256, 128, 224);

    cfg.gridDim = dim3(ab);
    cudaLaunchKernelEx(&cfg, k_agg<128, 32, true, false>,
                       (const __half*)linh, (const float*)linc, b1, (void*)hB, N);

    cfg.gridDim = dim3(3, gy);
    cudaLaunchKernelEx(&cfg, k_gemm_h<6>, (const __half*)hB, (const __half*)wt2,
                       bc2, linh, linc, N, 256, 176, 272);

    cfg.gridDim = dim3(ab);
    cudaLaunchKernelEx(&cfg, k_agg<176, 44, false, true>,
                       (const __half*)linh, (const float*)linc, b2, d_out, N);
}

// round 16
// speedup vs baseline: 1.1237x; 1.1237x over previous
#include <cuda_runtime.h>
#include <cuda_fp16.h>
#include <math.h>
#include <stdint.h>

#define NMAX   50000
#define EMAX   600000
#define OUTT   349

// ---------------- scratch (device globals) ----------------------------------
__device__ int    g_deg[NMAX];
__device__ float  g_dinv[NMAX];
__device__ int    g_off[NMAX];
__device__ int    g_cur[NMAX];
__device__ int    g_adj[EMAX];
__device__ float  g_adjd[EMAX];
__device__ int    g_total;
__device__ __half g_linh[(size_t)NMAX * 176];   // bases (fp16), pitch = NBF
__device__ float  g_linc[(size_t)NMAX * 96];    // comb (fp32), pitch = 96
__device__ __half g_xh[(size_t)NMAX * 128];
__device__ __half g_hA[(size_t)NMAX * 256];
__device__ __half g_hB[(size_t)NMAX * 256];
__device__ __half g_wt0[224 * 128];
__device__ __half g_wt1[224 * 256];
__device__ __half g_wt2[288 * 256];

// ---------------- PDL helpers --------------------------------------------------
__device__ __forceinline__ void gdc_wait()  { asm volatile("griddepcontrol.wait;" ::: "memory"); }
__device__ __forceinline__ void gdc_launch(){ asm volatile("griddepcontrol.launch_dependents;" ::: "memory"); }

// ---------------- converts ----------------------------------------------------
__device__ __forceinline__ void cvt_one(const float* Wb, const float* Wc, __half* Wt,
                                        int idx, int K, int NBF, int Ntot) {
    int n = idx / K, k = idx % K;
    float v = 0.0f;
    if (n < NBF)       v = Wb[k * NBF + n];
    else if (n < Ntot) v = Wc[k * (Ntot - NBF) + (n - NBF)];
    Wt[idx] = __float2half_rn(v);
}

__global__ void k_cvt_xw0(const float* __restrict__ x, __half2* __restrict__ xh, int n4,
                          const float* __restrict__ Wb0, const float* __restrict__ Wc0,
                          __half* __restrict__ wt0) {
    int i = blockIdx.x * blockDim.x + threadIdx.x;
    if (i < n4) {
        float4 v = reinterpret_cast<const float4*>(x)[i];
        xh[2 * i]     = __floats2half2_rn(v.x, v.y);
        xh[2 * i + 1] = __floats2half2_rn(v.z, v.w);
    } else {
        int idx = i - n4;
        if (idx < 224 * 128) cvt_one(Wb0, Wc0, wt0, idx, 128, 128, 224);
    }
    gdc_launch();
}

__global__ void k_cvt_w12(const float* __restrict__ Wb1, const float* __restrict__ Wc1,
                          const float* __restrict__ Wb2, const float* __restrict__ Wc2,
                          __half* __restrict__ wt1, __half* __restrict__ wt2) {
    const int S1 = 224 * 256, S2 = 288 * 256;
    int idx = blockIdx.x * blockDim.x + threadIdx.x;
    if (idx < S1)           cvt_one(Wb1, Wc1, wt1, idx,      256, 128, 224);
    else if (idx < S1 + S2) cvt_one(Wb2, Wc2, wt2, idx - S1, 256, 176, 272);
}

// ---------------- CSR build (scalar, high-occupancy, PDL edges) ---------------
__global__ void k_zero(int n) {
    int i = blockIdx.x * blockDim.x + threadIdx.x;
    if (i < n) g_deg[i] = 0;
    if (blockIdx.x == 0 && threadIdx.x == 0) g_total = 0;
    gdc_launch();
}

__global__ void k_deg(const int* __restrict__ row, int e) {
    int i = blockIdx.x * blockDim.x + threadIdx.x;
    int r = (i < e) ? row[i] : 0;
    gdc_wait();
    if (i < e) atomicAdd(&g_deg[r], 1);
    gdc_launch();
}

__global__ void k_off(int n) {
    int i = blockIdx.x * blockDim.x + threadIdx.x;
    int lane = threadIdx.x & 31;
    gdc_wait();
    int d = (i < n) ? g_deg[i] : 0;
    int s = d;
#pragma unroll
    for (int o = 1; o < 32; o <<= 1) {
        int u = __shfl_up_sync(0xffffffffu, s, o);
        if (lane >= o) s += u;
    }
    int total = __shfl_sync(0xffffffffu, s, 31);
    int base = 0;
    if (lane == 0) base = atomicAdd(&g_total, total);
    base = __shfl_sync(0xffffffffu, base, 0);
    if (i < n) {
        int off = base + s - d;
        g_off[i] = off;
        g_cur[i] = off;
        g_dinv[i] = (d > 0) ? rsqrtf((float)d) : 0.0f;
    }
    gdc_launch();
}

__global__ void k_scatter(const int* __restrict__ row, const int* __restrict__ col, int e) {
    int i = blockIdx.x * blockDim.x + threadIdx.x;
    int r = 0, c = 0;
    if (i < e) { r = row[i]; c = col[i]; }
    gdc_wait();
    if (i < e) {
        int p = atomicAdd(&g_cur[r], 1);
        g_adj[p]  = c;
        g_adjd[p] = g_dinv[c];
    }
}

// ---------------- fp16 tensor-core GEMM, cp.async + ldmatrix + PDL ------------
__device__ __forceinline__ void mma16(float* c, const uint32_t* a, const uint32_t* b) {
    asm volatile(
        "mma.sync.aligned.m16n8k16.row.col.f32.f16.f16.f32 "
        "{%0,%1,%2,%3}, {%4,%5,%6,%7}, {%8,%9}, {%0,%1,%2,%3};"
        : "+f"(c[0]), "+f"(c[1]), "+f"(c[2]), "+f"(c[3])
        : "r"(a[0]), "r"(a[1]), "r"(a[2]), "r"(a[3]), "r"(b[0]), "r"(b[1]));
}

__device__ __forceinline__ void cpa16(uint32_t saddr, const void* gptr, bool pred) {
    int sz = pred ? 16 : 0;
    asm volatile("cp.async.ca.shared.global [%0], [%1], 16, %2;"
                 :: "r"(saddr), "l"(gptr), "r"(sz));
}

__device__ __forceinline__ void ldsm4(uint32_t& a, uint32_t& b, uint32_t& c, uint32_t& d,
                                      uint32_t addr) {
    asm volatile("ldmatrix.sync.aligned.m8n8.x4.shared.b16 {%0,%1,%2,%3}, [%4];"
                 : "=r"(a), "=r"(b), "=r"(c), "=r"(d) : "r"(addr));
}
__device__ __forceinline__ void ldsm2(uint32_t& a, uint32_t& b, uint32_t addr) {
    asm volatile("ldmatrix.sync.aligned.m8n8.x2.shared.b16 {%0,%1}, [%2];"
                 : "=r"(a), "=r"(b) : "r"(addr));
}

template<int NT>
__global__ __launch_bounds__(256)
void k_gemm_h(const __half* __restrict__ A, const __half* __restrict__ Wt,
              const float* __restrict__ bc,
              __half* __restrict__ Ch, float* __restrict__ Cc,
              int M, int K, int NBF, int Ntot)
{
    constexpr int BN    = 16 * NT;
    constexpr int NPAIR = NT / 2;
    constexpr int TAIL  = NT & 1;
    __shared__ __align__(16) uint32_t As[4][128][12];
    __shared__ __align__(16) uint32_t Bs[4][BN][12];

    const int tid  = threadIdx.x;
    const int bm   = blockIdx.y * 128;
    const int bn   = blockIdx.x * BN;
    const int w    = tid >> 5, lane = tid & 31;
    const int wm   = w & 3,   wn   = w >> 2;
    const int g    = lane >> 2, t4 = lane & 3;

    const int crow = tid >> 1, ch = tid & 1;
    const bool aval = (bm + crow) < M;
    const __half* agp = A  + (size_t)(bm + crow) * K + ch * 8;
    const __half* bgp = Wt + (size_t)(bn + crow) * K + ch * 8;
    const bool bv = (tid < 2 * BN);

    uint32_t a_s = (uint32_t)__cvta_generic_to_shared(&As[0][crow][ch * 4]);
    uint32_t b_s = (uint32_t)__cvta_generic_to_shared(&Bs[0][crow][ch * 4]);
    constexpr uint32_t ASTRIDE = 128 * 12 * 4;
    constexpr uint32_t BSTRIDE = BN * 12 * 4;

    const int rm0 = wm * 32;
    const int cn0 = wn * NT * 8;

    const int arow = rm0 + ((lane >> 3) & 1) * 8 + (lane & 7);
    const int awrd = (lane >> 4) * 4;
    const uint32_t sA0 = (uint32_t)__cvta_generic_to_shared(&As[0][arow][awrd]);
    uint32_t sB[NPAIR + TAIL];
#pragma unroll
    for (int p = 0; p < NPAIR; p++) {
        int brow = cn0 + p * 16 + ((lane >> 4) & 1) * 8 + (lane & 7);
        int bwrd = ((lane >> 3) & 1) * 4;
        sB[p] = (uint32_t)__cvta_generic_to_shared(&Bs[0][brow][bwrd]);
    }
    if (TAIL) {
        int brow = cn0 + NPAIR * 16 + (lane & 7);
        int bwrd = ((lane >> 3) & 1) * 4;
        sB[NPAIR] = (uint32_t)__cvta_generic_to_shared(&Bs[0][brow][bwrd]);
    }

#define ISSUE(S, K0)                                                   \
    do {                                                               \
        cpa16(a_s + (S) * ASTRIDE, agp + (K0), aval);                  \
        if (bv) cpa16(b_s + (S) * BSTRIDE, bgp + (K0), true);          \
        asm volatile("cp.async.commit_group;");                        \
    } while (0)

    float acc[2][NT][4];
#pragma unroll
    for (int i = 0; i < 2; i++)
#pragma unroll
        for (int j = 0; j < NT; j++)
#pragma unroll
            for (int r = 0; r < 4; r++) acc[i][j][r] = 0.0f;

    gdc_wait();

    const int kiter = K >> 4;
    ISSUE(0, 0);
    ISSUE(1, 16);
    ISSUE(2, 32);

    for (int it = 0; it < kiter; it++) {
        asm volatile("cp.async.wait_group 2;");
        __syncthreads();
        const uint32_t aoff = (uint32_t)(it & 3) * ASTRIDE;
        const uint32_t boff = (uint32_t)(it & 3) * BSTRIDE;
        {
            uint32_t af0[4], af1[4];
            ldsm4(af0[0], af0[1], af0[2], af0[3], sA0 + aoff);
            ldsm4(af1[0], af1[1], af1[2], af1[3], sA0 + aoff + 16 * 48);
            uint32_t bf[NT][2];
#pragma unroll
            for (int p = 0; p < NPAIR; p++)
                ldsm4(bf[2 * p][0], bf[2 * p][1], bf[2 * p + 1][0], bf[2 * p + 1][1],
                      sB[p] + boff);
            if (TAIL)
                ldsm2(bf[NT - 1][0], bf[NT - 1][1], sB[NPAIR] + boff);
#pragma unroll
            for (int j = 0; j < NT; j++) {
                mma16(acc[0][j], af0, bf[j]);
                mma16(acc[1][j], af1, bf[j]);
            }
        }
        if (it + 3 < kiter) ISSUE((it + 3) & 3, (it + 3) * 16);
        else asm volatile("cp.async.commit_group;");
    }
#undef ISSUE

    gdc_launch();

    // ---- epilogue ----
#pragma unroll
    for (int i = 0; i < 2; i++) {
        int r0 = bm + rm0 + i * 16 + g;
#pragma unroll
        for (int j = 0; j < NT; j++) {
            int col = bn + cn0 + j * 8 + 2 * t4;
            if (col >= Ntot) continue;
            if (col < NBF) {
                if (r0 < M) {
                    __half2 h = __floats2half2_rn(acc[i][j][0], acc[i][j][1]);
                    *reinterpret_cast<__half2*>(&Ch[(size_t)r0 * NBF + col]) = h;
                }
                if (r0 + 8 < M) {
                    __half2 h = __floats2half2_rn(acc[i][j][2], acc[i][j][3]);
                    *reinterpret_cast<__half2*>(&Ch[(size_t)(r0 + 8) * NBF + col]) = h;
                }
            } else {
                int cc = col - NBF;
                float b0 = bc[cc], b1 = bc[cc + 1];
                if (r0 < M) {
                    float2 v = make_float2(acc[i][j][0] + b0, acc[i][j][1] + b1);
                    *reinterpret_cast<float2*>(&Cc[(size_t)r0 * 96 + cc]) = v;
                }
                if (r0 + 8 < M) {
                    float2 v = make_float2(acc[i][j][2] + b0, acc[i][j][3] + b1);
                    *reinterpret_cast<float2*>(&Cc[(size_t)(r0 + 8) * 96 + cc]) = v;
                }
            }
        }
    }
}

// ---------------- fused aggregation + combine + bias (+relu / +log_softmax) --
__device__ __forceinline__ float4 h4f(uint2 u) {
    __half2 a = *reinterpret_cast<__half2*>(&u.x);
    __half2 b = *reinterpret_cast<__half2*>(&u.y);
    float2 fa = __half22float2(a), fb = __half22float2(b);
    return make_float4(fa.x, fa.y, fb.x, fb.y);
}

// one batched aggregation step over NB edges starting at t (no masking)
template<int NBF, int NB>
__device__ __forceinline__ void agg_step(const __half* __restrict__ linh, int t, int lane,
                                         float4* vsym, float4* vsum, float4* vmax)
{
    constexpr int NH4 = NBF / 4;
    constexpr int C4  = (NH4 + 31) / 32;
    int cc[NB]; float dd[NB]; const uint2* sp[NB];
#pragma unroll
    for (int u = 0; u < NB; u++) {
        cc[u] = g_adj[t + u];
        dd[u] = g_adjd[t + u];
        sp[u] = reinterpret_cast<const uint2*>(linh + (size_t)cc[u] * NBF);
    }
#pragma unroll
    for (int q = 0; q < C4; q++) {
        int i4 = lane + q * 32;
        if (C4 > 1 && i4 >= NH4) break;
        float4 vv[NB];
#pragma unroll
        for (int u = 0; u < NB; u++) vv[u] = h4f(sp[u][i4]);
#pragma unroll
        for (int u = 0; u < NB; u++) {
            vsym[q].x += dd[u] * vv[u].x; vsym[q].y += dd[u] * vv[u].y;
            vsym[q].z += dd[u] * vv[u].z; vsym[q].w += dd[u] * vv[u].w;
            vsum[q].x += vv[u].x; vsum[q].y += vv[u].y;
            vsum[q].z += vv[u].z; vsum[q].w += vv[u].w;
            vmax[q].x = fmaxf(vmax[q].x, vv[u].x);
            vmax[q].y = fmaxf(vmax[q].y, vv[u].y);
            vmax[q].z = fmaxf(vmax[q].z, vv[u].z);
            vmax[q].w = fmaxf(vmax[q].w, vv[u].w);
        }
    }
}

template<int NBF, int F, bool RELU, bool LSM>
__global__ __launch_bounds__(256)
void k_agg(const __half* __restrict__ linh, const float* __restrict__ linc,
           const float* __restrict__ bias, void* __restrict__ out_v, int n)
{
    constexpr int HF  = 8 * F;
    constexpr int NI  = HF / 32;
    constexpr int NH4 = NBF / 4;
    constexpr int C4  = (NH4 + 31) / 32;
    constexpr int UN  = (C4 == 1) ? 8 : 4;
    __shared__ float agg_s[8][3 * NBF];
    __shared__ float comb_s[8][96];

    int gw   = (blockIdx.x * 256 + threadIdx.x) >> 5;
    int lane = threadIdx.x & 31;
    int lw   = threadIdx.x >> 5;
    if (gw >= n) { gdc_wait(); gdc_launch(); return; }

    int s = g_off[gw];
    int deg = g_deg[gw];
    int e = s + deg;

    float4 vsym[C4], vsum[C4], vmax[C4];
#pragma unroll
    for (int q = 0; q < C4; q++) {
        vsym[q] = make_float4(0.f, 0.f, 0.f, 0.f);
        vsum[q] = make_float4(0.f, 0.f, 0.f, 0.f);
        vmax[q] = make_float4(-INFINITY, -INFINITY, -INFINITY, -INFINITY);
    }

    gdc_wait();

    // main batched loop + descending-batch tail (4/2/1) — no serial edge chain
    int t = s;
    for (; t + UN <= e; t += UN)
        agg_step<NBF, UN>(linh, t, lane, vsym, vsum, vmax);
    int rem = e - t;
    if (UN == 8 && (rem & 4)) { agg_step<NBF, 4>(linh, t, lane, vsym, vsum, vmax); t += 4; }
    if (rem & 2)              { agg_step<NBF, 2>(linh, t, lane, vsym, vsum, vmax); t += 2; }
    if (rem & 1)              { agg_step<NBF, 1>(linh, t, lane, vsym, vsum, vmax); }

    gdc_launch();

    float dn   = g_dinv[gw];
    float invd = (deg > 0) ? (1.0f / (float)deg) : 0.0f;

    float4* arow0 = reinterpret_cast<float4*>(&agg_s[lw][0]);
    float4* arow1 = reinterpret_cast<float4*>(&agg_s[lw][NBF]);
    float4* arow2 = reinterpret_cast<float4*>(&agg_s[lw][2 * NBF]);
#pragma unroll
    for (int q = 0; q < C4; q++) {
        int i4 = lane + q * 32;
        if (C4 > 1 && i4 >= NH4) break;
        float4 sy = vsym[q];
        sy.x *= dn; sy.y *= dn; sy.z *= dn; sy.w *= dn;
        float4 me = vsum[q];
        me.x *= invd; me.y *= invd; me.z *= invd; me.w *= invd;
        float4 mx = vmax[q];
        if (deg == 0) mx = make_float4(0.f, 0.f, 0.f, 0.f);
        arow0[i4] = sy;
        arow1[i4] = me;
        arow2[i4] = mx;
    }

    const float* comb = linc + (size_t)gw * 96;
    comb_s[lw][lane]      = comb[lane];
    comb_s[lw][lane + 32] = comb[lane + 32];
    comb_s[lw][lane + 64] = comb[lane + 64];
    __syncwarp();

    float vals[NI];
#pragma unroll
    for (int i = 0; i < NI; i++) {
        int c = lane + i * 32;
        int h = c / F, f = c % F;
        float v = bias[c];
        const float* cb = &comb_s[lw][h * 12];
        const float* ag = &agg_s[lw][0];
#pragma unroll
        for (int k = 0; k < 12; k++) v = fmaf(cb[k], ag[k * F + f], v);
        if (RELU) v = fmaxf(v, 0.0f);
        vals[i] = v;
    }

    if (!LSM) {
        __half* out = (__half*)out_v;
#pragma unroll
        for (int i = 0; i < NI; i++)
            out[(size_t)gw * HF + lane + i * 32] = __float2half_rn(vals[i]);
    } else {
        float* out = (float*)out_v;
        float m = -INFINITY;
#pragma unroll
        for (int i = 0; i < NI; i++) {
            int c = lane + i * 32;
            m = fmaxf(m, (c < OUTT) ? vals[i] : -INFINITY);
        }
#pragma unroll
        for (int o = 16; o; o >>= 1) m = fmaxf(m, __shfl_xor_sync(0xffffffffu, m, o));
        float sum = 0.0f;
#pragma unroll
        for (int i = 0; i < NI; i++) {
            int c = lane + i * 32;
            if (c < OUTT) sum += expf(vals[i] - m);
        }
#pragma unroll
        for (int o = 16; o; o >>= 1) sum += __shfl_xor_sync(0xffffffffu, sum, o);
        float l = m + logf(sum);
#pragma unroll
        for (int i = 0; i < NI; i++) {
            int c = lane + i * 32;
            if (c < OUTT) out[(size_t)gw * OUTT + c] = vals[i] - l;
        }
    }
}

// ---------------- launch --------------------------------------------------------
extern "C" void kernel_launch(void* const* d_in, const int* in_sizes, int n_in,
                              void* d_out, int out_size)
{
    const float* x   = (const float*)d_in[0];
    const int*   ei  = (const int*)d_in[1];
    int N = in_sizes[0] / 128;
    int E = in_sizes[1] / 2;
    if (N > NMAX) N = NMAX;
    if (E > EMAX) E = EMAX;
    const int* row = ei;
    const int* col = ei + E;

    const float* Wb0 = (const float*)d_in[2];
    const float* Wc0 = (const float*)d_in[3];
    const float* bc0 = (const float*)d_in[4];
    const float* b0  = (const float*)d_in[5];
    const float* Wb1 = (const float*)d_in[6];
    const float* Wc1 = (const float*)d_in[7];
    const float* bc1 = (const float*)d_in[8];
    const float* b1  = (const float*)d_in[9];
    const float* Wb2 = (const float*)d_in[10];
    const float* Wc2 = (const float*)d_in[11];
    const float* bc2 = (const float*)d_in[12];
    const float* b2  = (const float*)d_in[13];

    __half* linh; float* linc; __half* xh; __half* hA; __half* hB;
    __half* wt0; __half* wt1; __half* wt2;
    cudaGetSymbolAddress((void**)&linh, g_linh);
    cudaGetSymbolAddress((void**)&linc, g_linc);
    cudaGetSymbolAddress((void**)&xh,   g_xh);
    cudaGetSymbolAddress((void**)&hA,   g_hA);
    cudaGetSymbolAddress((void**)&hB,   g_hB);
    cudaGetSymbolAddress((void**)&wt0,  g_wt0);
    cudaGetSymbolAddress((void**)&wt1,  g_wt1);
    cudaGetSymbolAddress((void**)&wt2,  g_wt2);

    const int T   = 256;
    const int gy  = (N + 127) / 128;
    const int ab  = (N + 7) / 8;
    const int n4  = N * 128 / 4;
    const int W12 = 224 * 256 + 288 * 256;
    const int XW0 = n4 + 224 * 128;

    // Streams/events created ONCE (first call is uncaptured).
    static cudaStream_t s1 = nullptr, s2 = nullptr;
    static cudaEvent_t evRoot = nullptr, evCsr = nullptr, evW12 = nullptr;
    if (!s1) {
        cudaStreamCreateWithFlags(&s1, cudaStreamNonBlocking);
        cudaStreamCreateWithFlags(&s2, cudaStreamNonBlocking);
        cudaEventCreateWithFlags(&evRoot, cudaEventDisableTiming);
        cudaEventCreateWithFlags(&evCsr,  cudaEventDisableTiming);
        cudaEventCreateWithFlags(&evW12,  cudaEventDisableTiming);
    }

    cudaEventRecord(evRoot, 0);
    cudaStreamWaitEvent(s1, evRoot, 0);
    cudaStreamWaitEvent(s2, evRoot, 0);

    // PDL attribute
    cudaLaunchAttribute attrs[1];
    attrs[0].id = cudaLaunchAttributeProgrammaticStreamSerialization;
    attrs[0].val.programmaticStreamSerializationAllowed = 1;

    // s1: CSR build, scalar kernels (full occupancy) + programmatic edges
    cudaLaunchConfig_t cfg1 = {};
    cfg1.stream = s1;
    cfg1.attrs = attrs;
    cfg1.numAttrs = 1;
    cfg1.blockDim = dim3(256);

    cfg1.gridDim = dim3((N + T - 1) / T);
    cudaLaunchKernelEx(&cfg1, k_zero, N);
    cfg1.gridDim = dim3((E + T - 1) / T);
    cudaLaunchKernelEx(&cfg1, k_deg, row, E);
    cfg1.gridDim = dim3((N + T - 1) / T);
    cudaLaunchKernelEx(&cfg1, k_off, N);
    cfg1.gridDim = dim3((E + T - 1) / T);
    cudaLaunchKernelEx(&cfg1, k_scatter, row, col, E);
    cudaEventRecord(evCsr, s1);

    // s2: layer-1/2 weight converts
    k_cvt_w12<<<(W12 + T - 1) / T, T, 0, s2>>>(Wb1, Wc1, Wb2, Wc2, wt1, wt2);
    cudaEventRecord(evW12, s2);

    // main chain (stream 0) with PDL edges
    cudaLaunchConfig_t cfg = {};
    cfg.stream = 0;
    cfg.attrs = attrs;
    cfg.numAttrs = 1;
    cfg.blockDim = dim3(256);

    k_cvt_xw0<<<(XW0 + T - 1) / T, T>>>(x, (__half2*)xh, n4, Wb0, Wc0, wt0);

    cfg.gridDim = dim3(2, gy);
    cudaLaunchKernelEx(&cfg, k_gemm_h<7>, (const __half*)xh, (const __half*)wt0,
                       bc0, linh, linc, N, 128, 128, 224);

    cudaStreamWaitEvent(0, evCsr, 0);
    cudaStreamWaitEvent(0, evW12, 0);

    cfg.gridDim = dim3(ab);
    cudaLaunchKernelEx(&cfg, k_agg<128, 32, true, false>,
                       (const __half*)linh, (const float*)linc, b0, (void*)hA, N);

    cfg.gridDim = dim3(2, gy);
    cudaLaunchKernelEx(&cfg, k_gemm_h<7>, (const __half*)hA, (const __half*)wt1,
                       bc1, linh, linc, N, 256, 128, 224);

    cfg.gridDim = dim3(ab);
    cudaLaunchKernelEx(&cfg, k_agg<128, 32, true, false>,
                       (const __half*)linh, (const float*)linc, b1, (void*)hB, N);

    cfg.gridDim = dim3(3, gy);
    cudaLaunchKernelEx(&cfg, k_gemm_h<6>, (const __half*)hB, (const __half*)wt2,
                       bc2, linh, linc, N, 256, 176, 272);

    cfg.gridDim = dim3(ab);
    cudaLaunchKernelEx(&cfg, k_agg<176, 44, false, true>,
                       (const __half*)linh, (const float*)linc, b2, d_out, N);
}

// round 17
// speedup vs baseline: 1.1321x; 1.0075x over previous
#include <cuda_runtime.h>
#include <cuda_fp16.h>
#include <math.h>
#include <stdint.h>

#define NMAX   50000
#define EMAX   600000
#define OUTT   349

// ---------------- scratch (device globals) ----------------------------------
__device__ int    g_deg[NMAX];
__device__ float  g_dinv[NMAX];
__device__ int    g_off[NMAX];
__device__ int    g_cur[NMAX];
__device__ int    g_adj[EMAX];
__device__ float  g_adjd[EMAX];
__device__ int    g_total;
__device__ __half g_linh[(size_t)NMAX * 176];   // bases (fp16), pitch = NBF
__device__ float  g_linc[(size_t)NMAX * 96];    // comb (fp32), pitch = 96
__device__ __half g_xh[(size_t)NMAX * 128];
__device__ __half g_hA[(size_t)NMAX * 256];
__device__ __half g_hB[(size_t)NMAX * 256];
__device__ __half g_wt0[224 * 128];
__device__ __half g_wt1[224 * 256];
__device__ __half g_wt2[288 * 256];

// ---------------- PDL helpers --------------------------------------------------
__device__ __forceinline__ void gdc_wait()  { asm volatile("griddepcontrol.wait;" ::: "memory"); }
__device__ __forceinline__ void gdc_launch(){ asm volatile("griddepcontrol.launch_dependents;" ::: "memory"); }

// ---------------- converts ----------------------------------------------------
__device__ __forceinline__ void cvt_one(const float* Wb, const float* Wc, __half* Wt,
                                        int idx, int K, int NBF, int Ntot) {
    int n = idx / K, k = idx % K;
    float v = 0.0f;
    if (n < NBF)       v = Wb[k * NBF + n];
    else if (n < Ntot) v = Wc[k * (Ntot - NBF) + (n - NBF)];
    Wt[idx] = __float2half_rn(v);
}

__global__ void k_cvt_xw0(const float* __restrict__ x, __half2* __restrict__ xh, int n4,
                          const float* __restrict__ Wb0, const float* __restrict__ Wc0,
                          __half* __restrict__ wt0) {
    int i = blockIdx.x * blockDim.x + threadIdx.x;
    if (i < n4) {
        float4 v = reinterpret_cast<const float4*>(x)[i];
        xh[2 * i]     = __floats2half2_rn(v.x, v.y);
        xh[2 * i + 1] = __floats2half2_rn(v.z, v.w);
    } else {
        int idx = i - n4;
        if (idx < 224 * 128) cvt_one(Wb0, Wc0, wt0, idx, 128, 128, 224);
    }
    gdc_launch();
}

__global__ void k_cvt_w12(const float* __restrict__ Wb1, const float* __restrict__ Wc1,
                          const float* __restrict__ Wb2, const float* __restrict__ Wc2,
                          __half* __restrict__ wt1, __half* __restrict__ wt2) {
    const int S1 = 224 * 256, S2 = 288 * 256;
    int idx = blockIdx.x * blockDim.x + threadIdx.x;
    if (idx < S1)           cvt_one(Wb1, Wc1, wt1, idx,      256, 128, 224);
    else if (idx < S1 + S2) cvt_one(Wb2, Wc2, wt2, idx - S1, 256, 176, 272);
}

// ---------------- CSR build (scalar, high-occupancy, PDL edges) ---------------
__global__ void k_zero(int n) {
    int i = blockIdx.x * blockDim.x + threadIdx.x;
    if (i < n) g_deg[i] = 0;
    if (blockIdx.x == 0 && threadIdx.x == 0) g_total = 0;
    gdc_launch();
}

__global__ void k_deg(const int* __restrict__ row, int e) {
    int i = blockIdx.x * blockDim.x + threadIdx.x;
    int r = (i < e) ? row[i] : 0;
    gdc_wait();
    if (i < e) atomicAdd(&g_deg[r], 1);
    gdc_launch();
}

__global__ void k_off(int n) {
    int i = blockIdx.x * blockDim.x + threadIdx.x;
    int lane = threadIdx.x & 31;
    gdc_wait();
    int d = (i < n) ? g_deg[i] : 0;
    int s = d;
#pragma unroll
    for (int o = 1; o < 32; o <<= 1) {
        int u = __shfl_up_sync(0xffffffffu, s, o);
        if (lane >= o) s += u;
    }
    int total = __shfl_sync(0xffffffffu, s, 31);
    int base = 0;
    if (lane == 0) base = atomicAdd(&g_total, total);
    base = __shfl_sync(0xffffffffu, base, 0);
    if (i < n) {
        int off = base + s - d;
        g_off[i] = off;
        g_cur[i] = off;
        g_dinv[i] = (d > 0) ? rsqrtf((float)d) : 0.0f;
    }
    gdc_launch();
}

__global__ void k_scatter(const int* __restrict__ row, const int* __restrict__ col, int e) {
    int i = blockIdx.x * blockDim.x + threadIdx.x;
    int r = 0, c = 0;
    if (i < e) { r = row[i]; c = col[i]; }
    gdc_wait();
    if (i < e) {
        int p = atomicAdd(&g_cur[r], 1);
        g_adj[p]  = c;
        g_adjd[p] = g_dinv[c];
    }
}

// ---------------- fp16 tensor-core GEMM, cp.async (3-stage) + ldmatrix + PDL --
__device__ __forceinline__ void mma16(float* c, const uint32_t* a, const uint32_t* b) {
    asm volatile(
        "mma.sync.aligned.m16n8k16.row.col.f32.f16.f16.f32 "
        "{%0,%1,%2,%3}, {%4,%5,%6,%7}, {%8,%9}, {%0,%1,%2,%3};"
        : "+f"(c[0]), "+f"(c[1]), "+f"(c[2]), "+f"(c[3])
        : "r"(a[0]), "r"(a[1]), "r"(a[2]), "r"(a[3]), "r"(b[0]), "r"(b[1]));
}

__device__ __forceinline__ void cpa16(uint32_t saddr, const void* gptr, bool pred) {
    int sz = pred ? 16 : 0;
    asm volatile("cp.async.ca.shared.global [%0], [%1], 16, %2;"
                 :: "r"(saddr), "l"(gptr), "r"(sz));
}

__device__ __forceinline__ void ldsm4(uint32_t& a, uint32_t& b, uint32_t& c, uint32_t& d,
                                      uint32_t addr) {
    asm volatile("ldmatrix.sync.aligned.m8n8.x4.shared.b16 {%0,%1,%2,%3}, [%4];"
                 : "=r"(a), "=r"(b), "=r"(c), "=r"(d) : "r"(addr));
}
__device__ __forceinline__ void ldsm2(uint32_t& a, uint32_t& b, uint32_t addr) {
    asm volatile("ldmatrix.sync.aligned.m8n8.x2.shared.b16 {%0,%1}, [%2];"
                 : "=r"(a), "=r"(b) : "r"(addr));
}

// 3-stage pipeline: 34.5KB smem/block -> 6 blocks/SM -> single wave at 782 blocks.
// Single-barrier safety: ISSUE at iter it writes buf (it+2)%3 == (it-1)%3, whose
// last reader finished before the barrier all warps just passed.
template<int NT>
__global__ __launch_bounds__(256)
void k_gemm_h(const __half* __restrict__ A, const __half* __restrict__ Wt,
              const float* __restrict__ bc,
              __half* __restrict__ Ch, float* __restrict__ Cc,
              int M, int K, int NBF, int Ntot)
{
    constexpr int BN    = 16 * NT;
    constexpr int NPAIR = NT / 2;
    constexpr int TAIL  = NT & 1;
    __shared__ __align__(16) uint32_t As[3][128][12];
    __shared__ __align__(16) uint32_t Bs[3][BN][12];

    const int tid  = threadIdx.x;
    const int bm   = blockIdx.y * 128;
    const int bn   = blockIdx.x * BN;
    const int w    = tid >> 5, lane = tid & 31;
    const int wm   = w & 3,   wn   = w >> 2;
    const int g    = lane >> 2, t4 = lane & 3;

    const int crow = tid >> 1, ch = tid & 1;
    const bool aval = (bm + crow) < M;
    const __half* agp = A  + (size_t)(bm + crow) * K + ch * 8;
    const __half* bgp = Wt + (size_t)(bn + crow) * K + ch * 8;
    const bool bv = (tid < 2 * BN);

    uint32_t a_s = (uint32_t)__cvta_generic_to_shared(&As[0][crow][ch * 4]);
    uint32_t b_s = (uint32_t)__cvta_generic_to_shared(&Bs[0][crow][ch * 4]);
    constexpr uint32_t ASTRIDE = 128 * 12 * 4;
    constexpr uint32_t BSTRIDE = BN * 12 * 4;

    const int rm0 = wm * 32;
    const int cn0 = wn * NT * 8;

    const int arow = rm0 + ((lane >> 3) & 1) * 8 + (lane & 7);
    const int awrd = (lane >> 4) * 4;
    const uint32_t sA0 = (uint32_t)__cvta_generic_to_shared(&As[0][arow][awrd]);
    uint32_t sB[NPAIR + TAIL];
#pragma unroll
    for (int p = 0; p < NPAIR; p++) {
        int brow = cn0 + p * 16 + ((lane >> 4) & 1) * 8 + (lane & 7);
        int bwrd = ((lane >> 3) & 1) * 4;
        sB[p] = (uint32_t)__cvta_generic_to_shared(&Bs[0][brow][bwrd]);
    }
    if (TAIL) {
        int brow = cn0 + NPAIR * 16 + (lane & 7);
        int bwrd = ((lane >> 3) & 1) * 4;
        sB[NPAIR] = (uint32_t)__cvta_generic_to_shared(&Bs[0][brow][bwrd]);
    }

#define ISSUE(S, K0)                                                   \
    do {                                                               \
        cpa16(a_s + (S) * ASTRIDE, agp + (K0), aval);                  \
        if (bv) cpa16(b_s + (S) * BSTRIDE, bgp + (K0), true);          \
        asm volatile("cp.async.commit_group;");                        \
    } while (0)

    float acc[2][NT][4];
#pragma unroll
    for (int i = 0; i < 2; i++)
#pragma unroll
        for (int j = 0; j < NT; j++)
#pragma unroll
            for (int r = 0; r < 4; r++) acc[i][j][r] = 0.0f;

    gdc_wait();

    const int kiter = K >> 4;
    ISSUE(0, 0);
    ISSUE(1, 16);

    int buf = 0, nbuf = 2;     // nbuf = (it+2) % 3, maintained incrementally
    for (int it = 0; it < kiter; it++) {
        asm volatile("cp.async.wait_group 1;");
        __syncthreads();
        const uint32_t aoff = (uint32_t)buf * ASTRIDE;
        const uint32_t boff = (uint32_t)buf * BSTRIDE;
        {
            uint32_t af0[4], af1[4];
            ldsm4(af0[0], af0[1], af0[2], af0[3], sA0 + aoff);
            ldsm4(af1[0], af1[1], af1[2], af1[3], sA0 + aoff + 16 * 48);
            uint32_t bf[NT][2];
#pragma unroll
            for (int p = 0; p < NPAIR; p++)
                ldsm4(bf[2 * p][0], bf[2 * p][1], bf[2 * p + 1][0], bf[2 * p + 1][1],
                      sB[p] + boff);
            if (TAIL)
                ldsm2(bf[NT - 1][0], bf[NT - 1][1], sB[NPAIR] + boff);
#pragma unroll
            for (int j = 0; j < NT; j++) {
                mma16(acc[0][j], af0, bf[j]);
                mma16(acc[1][j], af1, bf[j]);
            }
        }
        if (it + 2 < kiter) ISSUE(nbuf, (it + 2) * 16);
        else asm volatile("cp.async.commit_group;");
        buf  = (buf  == 2) ? 0 : buf + 1;
        nbuf = (nbuf == 2) ? 0 : nbuf + 1;
    }
#undef ISSUE

    gdc_launch();

    // ---- epilogue ----
#pragma unroll
    for (int i = 0; i < 2; i++) {
        int r0 = bm + rm0 + i * 16 + g;
#pragma unroll
        for (int j = 0; j < NT; j++) {
            int col = bn + cn0 + j * 8 + 2 * t4;
            if (col >= Ntot) continue;
            if (col < NBF) {
                if (r0 < M) {
                    __half2 h = __floats2half2_rn(acc[i][j][0], acc[i][j][1]);
                    *reinterpret_cast<__half2*>(&Ch[(size_t)r0 * NBF + col]) = h;
                }
                if (r0 + 8 < M) {
                    __half2 h = __floats2half2_rn(acc[i][j][2], acc[i][j][3]);
                    *reinterpret_cast<__half2*>(&Ch[(size_t)(r0 + 8) * NBF + col]) = h;
                }
            } else {
                int cc = col - NBF;
                float b0 = bc[cc], b1 = bc[cc + 1];
                if (r0 < M) {
                    float2 v = make_float2(acc[i][j][0] + b0, acc[i][j][1] + b1);
                    *reinterpret_cast<float2*>(&Cc[(size_t)r0 * 96 + cc]) = v;
                }
                if (r0 + 8 < M) {
                    float2 v = make_float2(acc[i][j][2] + b0, acc[i][j][3] + b1);
                    *reinterpret_cast<float2*>(&Cc[(size_t)(r0 + 8) * 96 + cc]) = v;
                }
            }
        }
    }
}

// ---------------- fused aggregation + combine + bias (+relu / +log_softmax) --
__device__ __forceinline__ float4 h4f(uint2 u) {
    __half2 a = *reinterpret_cast<__half2*>(&u.x);
    __half2 b = *reinterpret_cast<__half2*>(&u.y);
    float2 fa = __half22float2(a), fb = __half22float2(b);
    return make_float4(fa.x, fa.y, fb.x, fb.y);
}

// one batched aggregation step over NB edges starting at t (no masking)
template<int NBF, int NB>
__device__ __forceinline__ void agg_step(const __half* __restrict__ linh, int t, int lane,
                                         float4* vsym, float4* vsum, float4* vmax)
{
    constexpr int NH4 = NBF / 4;
    constexpr int C4  = (NH4 + 31) / 32;
    int cc[NB]; float dd[NB]; const uint2* sp[NB];
#pragma unroll
    for (int u = 0; u < NB; u++) {
        cc[u] = g_adj[t + u];
        dd[u] = g_adjd[t + u];
        sp[u] = reinterpret_cast<const uint2*>(linh + (size_t)cc[u] * NBF);
    }
#pragma unroll
    for (int q = 0; q < C4; q++) {
        int i4 = lane + q * 32;
        if (C4 > 1 && i4 >= NH4) break;
        float4 vv[NB];
#pragma unroll
        for (int u = 0; u < NB; u++) vv[u] = h4f(sp[u][i4]);
#pragma unroll
        for (int u = 0; u < NB; u++) {
            vsym[q].x += dd[u] * vv[u].x; vsym[q].y += dd[u] * vv[u].y;
            vsym[q].z += dd[u] * vv[u].z; vsym[q].w += dd[u] * vv[u].w;
            vsum[q].x += vv[u].x; vsum[q].y += vv[u].y;
            vsum[q].z += vv[u].z; vsum[q].w += vv[u].w;
            vmax[q].x = fmaxf(vmax[q].x, vv[u].x);
            vmax[q].y = fmaxf(vmax[q].y, vv[u].y);
            vmax[q].z = fmaxf(vmax[q].z, vv[u].z);
            vmax[q].w = fmaxf(vmax[q].w, vv[u].w);
        }
    }
}

template<int NBF, int F, bool RELU, bool LSM>
__global__ __launch_bounds__(256)
void k_agg(const __half* __restrict__ linh, const float* __restrict__ linc,
           const float* __restrict__ bias, void* __restrict__ out_v, int n)
{
    constexpr int HF  = 8 * F;
    constexpr int NI  = HF / 32;
    constexpr int NH4 = NBF / 4;
    constexpr int C4  = (NH4 + 31) / 32;
    constexpr int UN  = 8;
    __shared__ float agg_s[8][3 * NBF];
    __shared__ float comb_s[8][96];

    int gw   = (blockIdx.x * 256 + threadIdx.x) >> 5;
    int lane = threadIdx.x & 31;
    int lw   = threadIdx.x >> 5;
    if (gw >= n) { gdc_wait(); gdc_launch(); return; }

    int s = g_off[gw];
    int deg = g_deg[gw];
    int e = s + deg;

    float4 vsym[C4], vsum[C4], vmax[C4];
#pragma unroll
    for (int q = 0; q < C4; q++) {
        vsym[q] = make_float4(0.f, 0.f, 0.f, 0.f);
        vsum[q] = make_float4(0.f, 0.f, 0.f, 0.f);
        vmax[q] = make_float4(-INFINITY, -INFINITY, -INFINITY, -INFINITY);
    }

    gdc_wait();

    // main batched loop + descending-batch tail (4/2/1) — no serial edge chain
    int t = s;
    for (; t + UN <= e; t += UN)
        agg_step<NBF, UN>(linh, t, lane, vsym, vsum, vmax);
    int rem = e - t;
    if (rem & 4) { agg_step<NBF, 4>(linh, t, lane, vsym, vsum, vmax); t += 4; }
    if (rem & 2) { agg_step<NBF, 2>(linh, t, lane, vsym, vsum, vmax); t += 2; }
    if (rem & 1) { agg_step<NBF, 1>(linh, t, lane, vsym, vsum, vmax); }

    gdc_launch();

    float dn   = g_dinv[gw];
    float invd = (deg > 0) ? (1.0f / (float)deg) : 0.0f;

    float4* arow0 = reinterpret_cast<float4*>(&agg_s[lw][0]);
    float4* arow1 = reinterpret_cast<float4*>(&agg_s[lw][NBF]);
    float4* arow2 = reinterpret_cast<float4*>(&agg_s[lw][2 * NBF]);
#pragma unroll
    for (int q = 0; q < C4; q++) {
        int i4 = lane + q * 32;
        if (C4 > 1 && i4 >= NH4) break;
        float4 sy = vsym[q];
        sy.x *= dn; sy.y *= dn; sy.z *= dn; sy.w *= dn;
        float4 me = vsum[q];
        me.x *= invd; me.y *= invd; me.z *= invd; me.w *= invd;
        float4 mx = vmax[q];
        if (deg == 0) mx = make_float4(0.f, 0.f, 0.f, 0.f);
        arow0[i4] = sy;
        arow1[i4] = me;
        arow2[i4] = mx;
    }

    const float* comb = linc + (size_t)gw * 96;
    comb_s[lw][lane]      = comb[lane];
    comb_s[lw][lane + 32] = comb[lane + 32];
    comb_s[lw][lane + 64] = comb[lane + 64];
    __syncwarp();

    float vals[NI];
#pragma unroll
    for (int i = 0; i < NI; i++) {
        int c = lane + i * 32;
        int h = c / F, f = c % F;
        float v = bias[c];
        const float* cb = &comb_s[lw][h * 12];
        const float* ag = &agg_s[lw][0];
#pragma unroll
        for (int k = 0; k < 12; k++) v = fmaf(cb[k], ag[k * F + f], v);
        if (RELU) v = fmaxf(v, 0.0f);
        vals[i] = v;
    }

    if (!LSM) {
        __half* out = (__half*)out_v;
#pragma unroll
        for (int i = 0; i < NI; i++)
            out[(size_t)gw * HF + lane + i * 32] = __float2half_rn(vals[i]);
    } else {
        float* out = (float*)out_v;
        float m = -INFINITY;
#pragma unroll
        for (int i = 0; i < NI; i++) {
            int c = lane + i * 32;
            m = fmaxf(m, (c < OUTT) ? vals[i] : -INFINITY);
        }
#pragma unroll
        for (int o = 16; o; o >>= 1) m = fmaxf(m, __shfl_xor_sync(0xffffffffu, m, o));
        float sum = 0.0f;
#pragma unroll
        for (int i = 0; i < NI; i++) {
            int c = lane + i * 32;
            if (c < OUTT) sum += expf(vals[i] - m);
        }
#pragma unroll
        for (int o = 16; o; o >>= 1) sum += __shfl_xor_sync(0xffffffffu, sum, o);
        float l = m + logf(sum);
#pragma unroll
        for (int i = 0; i < NI; i++) {
            int c = lane + i * 32;
            if (c < OUTT) out[(size_t)gw * OUTT + c] = vals[i] - l;
        }
    }
}

// ---------------- launch --------------------------------------------------------
extern "C" void kernel_launch(void* const* d_in, const int* in_sizes, int n_in,
                              void* d_out, int out_size)
{
    const float* x   = (const float*)d_in[0];
    const int*   ei  = (const int*)d_in[1];
    int N = in_sizes[0] / 128;
    int E = in_sizes[1] / 2;
    if (N > NMAX) N = NMAX;
    if (E > EMAX) E = EMAX;
    const int* row = ei;
    const int* col = ei + E;

    const float* Wb0 = (const float*)d_in[2];
    const float* Wc0 = (const float*)d_in[3];
    const float* bc0 = (const float*)d_in[4];
    const float* b0  = (const float*)d_in[5];
    const float* Wb1 = (const float*)d_in[6];
    const float* Wc1 = (const float*)d_in[7];
    const float* bc1 = (const float*)d_in[8];
    const float* b1  = (const float*)d_in[9];
    const float* Wb2 = (const float*)d_in[10];
    const float* Wc2 = (const float*)d_in[11];
    const float* bc2 = (const float*)d_in[12];
    const float* b2  = (const float*)d_in[13];

    __half* linh; float* linc; __half* xh; __half* hA; __half* hB;
    __half* wt0; __half* wt1; __half* wt2;
    cudaGetSymbolAddress((void**)&linh, g_linh);
    cudaGetSymbolAddress((void**)&linc, g_linc);
    cudaGetSymbolAddress((void**)&xh,   g_xh);
    cudaGetSymbolAddress((void**)&hA,   g_hA);
    cudaGetSymbolAddress((void**)&hB,   g_hB);
    cudaGetSymbolAddress((void**)&wt0,  g_wt0);
    cudaGetSymbolAddress((void**)&wt1,  g_wt1);
    cudaGetSymbolAddress((void**)&wt2,  g_wt2);

    const int T   = 256;
    const int gy  = (N + 127) / 128;
    const int ab  = (N + 7) / 8;
    const int n4  = N * 128 / 4;
    const int W12 = 224 * 256 + 288 * 256;
    const int XW0 = n4 + 224 * 128;

    // Streams/events created ONCE (first call is uncaptured).
    static cudaStream_t s1 = nullptr, s2 = nullptr;
    static cudaEvent_t evRoot = nullptr, evCsr = nullptr, evW12 = nullptr;
    if (!s1) {
        cudaStreamCreateWithFlags(&s1, cudaStreamNonBlocking);
        cudaStreamCreateWithFlags(&s2, cudaStreamNonBlocking);
        cudaEventCreateWithFlags(&evRoot, cudaEventDisableTiming);
        cudaEventCreateWithFlags(&evCsr,  cudaEventDisableTiming);
        cudaEventCreateWithFlags(&evW12,  cudaEventDisableTiming);
    }

    cudaEventRecord(evRoot, 0);
    cudaStreamWaitEvent(s1, evRoot, 0);
    cudaStreamWaitEvent(s2, evRoot, 0);

    // PDL attribute
    cudaLaunchAttribute attrs[1];
    attrs[0].id = cudaLaunchAttributeProgrammaticStreamSerialization;
    attrs[0].val.programmaticStreamSerializationAllowed = 1;

    // s1: CSR build, scalar kernels (full occupancy) + programmatic edges
    cudaLaunchConfig_t cfg1 = {};
    cfg1.stream = s1;
    cfg1.attrs = attrs;
    cfg1.numAttrs = 1;
    cfg1.blockDim = dim3(256);

    cfg1.gridDim = dim3((N + T - 1) / T);
    cudaLaunchKernelEx(&cfg1, k_zero, N);
    cfg1.gridDim = dim3((E + T - 1) / T);
    cudaLaunchKernelEx(&cfg1, k_deg, row, E);
    cfg1.gridDim = dim3((N + T - 1) / T);
    cudaLaunchKernelEx(&cfg1, k_off, N);
    cfg1.gridDim = dim3((E + T - 1) / T);
    cudaLaunchKernelEx(&cfg1, k_scatter, row, col, E);
    cudaEventRecord(evCsr, s1);

    // s2: layer-1/2 weight converts
    k_cvt_w12<<<(W12 + T - 1) / T, T, 0, s2>>>(Wb1, Wc1, Wb2, Wc2, wt1, wt2);
    cudaEventRecord(evW12, s2);

    // main chain (stream 0) with PDL edges
    cudaLaunchConfig_t cfg = {};
    cfg.stream = 0;
    cfg.attrs = attrs;
    cfg.numAttrs = 1;
    cfg.blockDim = dim3(256);

    k_cvt_xw0<<<(XW0 + T - 1) / T, T>>>(x, (__half2*)xh, n4, Wb0, Wc0, wt0);

    cfg.gridDim = dim3(2, gy);
    cudaLaunchKernelEx(&cfg, k_gemm_h<7>, (const __half*)xh, (const __half*)wt0,
                       bc0, linh, linc, N, 128, 128, 224);

    cudaStreamWaitEvent(0, evCsr, 0);
    cudaStreamWaitEvent(0, evW12, 0);

    cfg.gridDim = dim3(ab);
    cudaLaunchKernelEx(&cfg, k_agg<128, 32, true, false>,
                       (const __half*)linh, (const float*)linc, b0, (void*)hA, N);

    cfg.gridDim = dim3(2, gy);
    cudaLaunchKernelEx(&cfg, k_gemm_h<7>, (const __half*)hA, (const __half*)wt1,
                       bc1, linh, linc, N, 256, 128, 224);

    cfg.gridDim = dim3(ab);
    cudaLaunchKernelEx(&cfg, k_agg<128, 32, true, false>,
                       (const __half*)linh, (const float*)linc, b1, (void*)hB, N);

    cfg.gridDim = dim3(3, gy);
    cudaLaunchKernelEx(&cfg, k_gemm_h<6>, (const __half*)hB, (const __half*)wt2,
                       bc2, linh, linc, N, 256, 176, 272);

    cfg.gridDim = dim3(ab);
    cudaLaunchKernelEx(&cfg, k_agg<176, 44, false, true>,
                       (const __half*)linh, (const float*)linc, b2, d_out, N);
}